// round 1
// baseline (speedup 1.0000x reference)
#include <cuda_runtime.h>
#include <math.h>

// Problem constants
#define Nn   32
#define Cc   64
#define Tt   64
#define Vv   204
#define Hh   3
#define QKd  16
#define Pp   (Tt * Vv)        // 13056 = 64 * 204
#define OQKV (2 * Hh * QKd)   // 96
#define HC   (Hh * Cc)        // 192

// ---------------- scratch (device globals; no runtime allocation) ----------------
__device__ float d_h  [(size_t)Nn * Cc * Pp];     // gcn conv out, later reused as z
__device__ float d_g  [(size_t)Nn * Cc * Pp];     // relu(bn(adj)+x)
__device__ float d_qk [(size_t)Nn * OQKV * Pp];   // qkv conv out
__device__ float d_wpe[(size_t)OQKV * Pp];        // qkv_w @ pe + qkv_b
__device__ float d_att[(size_t)Nn * Hh * Tt * Tt];
__device__ float d_y  [(size_t)Nn * HC * Pp];     // einsum('nctv,nstq->nscqv')

enum { MODE_BIAS = 0, MODE_ADD2D = 1, MODE_BN_RES_LEAKY = 2 };

// ---------------- generic 1x1 conv over channels: out[n,o,p] = sum_c W[o,c]*in[n,c,p] ----------------
// grid: (P/64, ceil(Oc/64), nb), block 256. 64x64 tile, 4x4 microtile, k-chunks of 16.
template <int MODE>
__global__ void conv1x1_kernel(const float* __restrict__ in,   // [nb, Kc, P]
                               const float* __restrict__ W,    // [Oc, Kc]
                               const float* __restrict__ bias, // [Oc]
                               const float* __restrict__ add2d,// [Oc, P]   (MODE_ADD2D)
                               const float* __restrict__ res,  // [nb, Oc, P] (MODE_BN_RES_LEAKY)
                               const float* __restrict__ bng,
                               const float* __restrict__ bnb,
                               const float* __restrict__ bnm,
                               const float* __restrict__ bnv,
                               float* __restrict__ out,
                               int Kc, int Oc)
{
    __shared__ float Ws[16][64];
    __shared__ float Is[16][64];

    const int n   = blockIdx.z;
    const int pt  = blockIdx.x * 64;
    const int ot  = blockIdx.y * 64;
    const int tid = threadIdx.x;
    const int p0  = (tid & 15) * 4;
    const int o0  = (tid >> 4) * 4;

    const float* inN = in + (size_t)n * Kc * Pp;

    float acc[4][4] = {};

    for (int kb = 0; kb < Kc; kb += 16) {
        #pragma unroll
        for (int i = 0; i < 4; i++) {
            int e = tid + 256 * i;          // 0..1023
            int k = e >> 6;                 // 0..15
            int x = e & 63;                 // 0..63
            int og = ot + x;
            Ws[k][x] = (og < Oc) ? W[(size_t)og * Kc + kb + k] : 0.f;
            Is[k][x] = inN[(size_t)(kb + k) * Pp + pt + x];
        }
        __syncthreads();
        #pragma unroll
        for (int k = 0; k < 16; k++) {
            float4 wv = *(const float4*)&Ws[k][o0];
            float4 iv = *(const float4*)&Is[k][p0];
            float w[4] = {wv.x, wv.y, wv.z, wv.w};
            float v4[4] = {iv.x, iv.y, iv.z, iv.w};
            #pragma unroll
            for (int i = 0; i < 4; i++)
                #pragma unroll
                for (int j = 0; j < 4; j++)
                    acc[i][j] = fmaf(w[i], v4[j], acc[i][j]);
        }
        __syncthreads();
    }

    #pragma unroll
    for (int i = 0; i < 4; i++) {
        int o = ot + o0 + i;
        if (o >= Oc) continue;
        size_t obase = ((size_t)n * Oc + o) * Pp + pt + p0;
        if (MODE == MODE_BIAS) {
            float b = bias[o];
            #pragma unroll
            for (int j = 0; j < 4; j++)
                out[obase + j] = acc[i][j] + b;
        } else if (MODE == MODE_ADD2D) {
            size_t abase = (size_t)o * Pp + pt + p0;
            #pragma unroll
            for (int j = 0; j < 4; j++)
                out[obase + j] = acc[i][j] + add2d[abase + j];
        } else { // MODE_BN_RES_LEAKY
            float b  = bias[o];
            float s  = bng[o] * rsqrtf(bnv[o] + 1e-5f);
            float sh = bnb[o] - bnm[o] * s;
            #pragma unroll
            for (int j = 0; j < 4; j++) {
                float val = (acc[i][j] + b) * s + sh + res[obase + j];
                out[obase + j] = (val > 0.f) ? val : 0.1f * val;
            }
        }
    }
}

// ---------------- adjacency + BN + residual + relu ----------------
// g[r,u] = relu( bn_c( sum_v h[r,v]*A[u,v] ) + x[r,u] ),  r = n*C*T + c*T + t (131072 rows)
// grid: (ceil(204/64)=4, 131072/64=2048), block 256.
__global__ void adj_bn_relu_kernel(const float* __restrict__ h,
                                   const float* __restrict__ A,   // [204,204]
                                   const float* __restrict__ x,
                                   const float* __restrict__ bng,
                                   const float* __restrict__ bnb,
                                   const float* __restrict__ bnm,
                                   const float* __restrict__ bnv,
                                   float* __restrict__ out)
{
    __shared__ float Hs[16][68];   // [k(v)][r]
    __shared__ float As[16][68];   // [k(v)][u]

    const int ut  = blockIdx.x * 64;
    const int rt  = blockIdx.y * 64;
    const int tid = threadIdx.x;
    const int r0  = (tid >> 4) * 4;
    const int u0  = (tid & 15) * 4;

    float acc[4][4] = {};

    for (int vb = 0; vb < Vv; vb += 16) {
        #pragma unroll
        for (int i = 0; i < 4; i++) {
            int e = tid + 256 * i;
            // H: coalesced 16-float rows
            int k = e & 15, r = e >> 4;
            int v = vb + k;
            Hs[k][r] = (v < Vv) ? h[(size_t)(rt + r) * Vv + v] : 0.f;
            // A: [k][u]
            int u = e & 63, kk = e >> 6;
            int vg = vb + kk, ug = ut + u;
            As[kk][u] = (vg < Vv && ug < Vv) ? A[(size_t)ug * Vv + vg] : 0.f;
        }
        __syncthreads();
        #pragma unroll
        for (int k = 0; k < 16; k++) {
            float4 hv = *(const float4*)&Hs[k][r0];
            float4 av = *(const float4*)&As[k][u0];
            float hh[4] = {hv.x, hv.y, hv.z, hv.w};
            float aa[4] = {av.x, av.y, av.z, av.w};
            #pragma unroll
            for (int i = 0; i < 4; i++)
                #pragma unroll
                for (int j = 0; j < 4; j++)
                    acc[i][j] = fmaf(hh[i], aa[j], acc[i][j]);
        }
        __syncthreads();
    }

    #pragma unroll
    for (int i = 0; i < 4; i++) {
        int row = rt + r0 + i;
        int c = (row >> 6) & 63;
        float s  = bng[c] * rsqrtf(bnv[c] + 1e-5f);
        float sh = bnb[c] - bnm[c] * s;
        #pragma unroll
        for (int j = 0; j < 4; j++) {
            int u = ut + u0 + j;
            if (u < Vv) {
                float val = acc[i][j] * s + sh + x[(size_t)row * Vv + u];
                out[(size_t)row * Vv + u] = fmaxf(val, 0.f);
            }
        }
    }
}

// ---------------- attention scores ----------------
// att[n,h,t,q] = tanh( sum_{c,v} q[c,t,v]*k[c,q,v] / 3264 ) * alpha[h] + att1s[h,t,q]
// grid: (H=3, N=32), block 256. Output 64x64 per CTA, K = 16*204.
__global__ void attn_kernel(const float* __restrict__ qk,
                            const float* __restrict__ alphas,
                            const float* __restrict__ att1s,
                            float* __restrict__ att)
{
    __shared__ float Qs[32][68];  // [vv][t]
    __shared__ float Ks[32][68];  // [vv][q]

    const int hh = blockIdx.x;
    const int n  = blockIdx.y;
    const int tid = threadIdx.x;
    const int t0 = (tid >> 4) * 4;
    const int q0 = (tid & 15) * 4;

    const float* qb = qk + ((size_t)n * OQKV + hh * QKd) * Pp;
    const float* kb = qk + ((size_t)n * OQKV + Hh * QKd + hh * QKd) * Pp;

    float acc[4][4] = {};

    for (int c = 0; c < QKd; c++) {
        for (int vb = 0; vb < Vv; vb += 32) {
            #pragma unroll
            for (int i = 0; i < 8; i++) {
                int e  = tid + 256 * i;     // 0..2047
                int vv = e & 31;
                int t  = e >> 5;            // 0..63
                int v  = vb + vv;
                bool ok = (v < Vv);
                Qs[vv][t] = ok ? qb[(size_t)c * Pp + t * Vv + v] : 0.f;
                Ks[vv][t] = ok ? kb[(size_t)c * Pp + t * Vv + v] : 0.f;
            }
            __syncthreads();
            #pragma unroll
            for (int vv = 0; vv < 32; vv++) {
                float4 qv = *(const float4*)&Qs[vv][t0];
                float4 kv = *(const float4*)&Ks[vv][q0];
                float qq[4] = {qv.x, qv.y, qv.z, qv.w};
                float kk[4] = {kv.x, kv.y, kv.z, kv.w};
                #pragma unroll
                for (int i = 0; i < 4; i++)
                    #pragma unroll
                    for (int j = 0; j < 4; j++)
                        acc[i][j] = fmaf(qq[i], kk[j], acc[i][j]);
            }
            __syncthreads();
        }
    }

    const float al = alphas[hh];
    const float inv = 1.0f / (float)(QKd * Vv);
    #pragma unroll
    for (int i = 0; i < 4; i++) {
        int t = t0 + i;
        #pragma unroll
        for (int j = 0; j < 4; j++) {
            int q = q0 + j;
            float val = tanhf(acc[i][j] * inv) * al + att1s[((size_t)hh * Tt + t) * Tt + q];
            att[(((size_t)n * Hh + hh) * Tt + t) * Tt + q] = val;
        }
    }
}

// ---------------- y = einsum('nctv,nstq->nscqv') ----------------
// y[n, s*C+c, q, v] = sum_t g[n,c,t,v] * att[n,s,t,q]
// grid: (4 v-tiles, 192 = s*64+c, 32 = n), block 256.
__global__ void y_kernel(const float* __restrict__ g,
                         const float* __restrict__ att,
                         float* __restrict__ y)
{
    __shared__ float As[64][68];  // [t][q]
    __shared__ float Gs[64][68];  // [t][v]

    const int vt = blockIdx.x * 64;
    const int sc = blockIdx.y;            // s*64 + c
    const int s  = sc >> 6;
    const int c  = sc & 63;
    const int n  = blockIdx.z;
    const int tid = threadIdx.x;
    const int q0 = (tid >> 4) * 4;
    const int v0 = (tid & 15) * 4;

    const float* attB = att + (((size_t)n * Hh + s) * Tt) * Tt;
    const float* gB   = g + ((size_t)n * Cc + c) * Pp;

    #pragma unroll
    for (int i = 0; i < 16; i++) {
        int e = tid + 256 * i;   // 0..4095
        int t = e >> 6;
        int j = e & 63;
        As[t][j] = attB[(size_t)t * Tt + j];
        int v = vt + j;
        Gs[t][j] = (v < Vv) ? gB[(size_t)t * Vv + v] : 0.f;
    }
    __syncthreads();

    float acc[4][4] = {};
    #pragma unroll
    for (int t = 0; t < 64; t++) {
        float4 av = *(const float4*)&As[t][q0];
        float4 gv = *(const float4*)&Gs[t][v0];
        float aa[4] = {av.x, av.y, av.z, av.w};
        float gg[4] = {gv.x, gv.y, gv.z, gv.w};
        #pragma unroll
        for (int i = 0; i < 4; i++)
            #pragma unroll
            for (int j = 0; j < 4; j++)
                acc[i][j] = fmaf(aa[i], gg[j], acc[i][j]);
    }

    #pragma unroll
    for (int i = 0; i < 4; i++) {
        int q = q0 + i;
        size_t base = (((size_t)n * HC + sc) * Tt + q) * Vv;
        #pragma unroll
        for (int j = 0; j < 4; j++) {
            int v = vt + v0 + j;
            if (v < Vv) y[base + v] = acc[i][j];
        }
    }
}

// ---------------- launch ----------------
extern "C" void kernel_launch(void* const* d_in, const int* in_sizes, int n_in,
                              void* d_out, int out_size)
{
    const float* x      = (const float*)d_in[0];
    const float* A      = (const float*)d_in[1];
    const float* gcn_w  = (const float*)d_in[2];
    const float* gcn_b  = (const float*)d_in[3];
    const float* gcn_g  = (const float*)d_in[4];
    const float* gcn_bb = (const float*)d_in[5];
    const float* gcn_m  = (const float*)d_in[6];
    const float* gcn_v  = (const float*)d_in[7];
    const float* pe     = (const float*)d_in[8];
    const float* qkv_w  = (const float*)d_in[9];
    const float* qkv_b  = (const float*)d_in[10];
    const float* alphas = (const float*)d_in[11];
    const float* att1s  = (const float*)d_in[12];
    const float* on_w   = (const float*)d_in[13];
    const float* on_b   = (const float*)d_in[14];
    const float* on_g   = (const float*)d_in[15];
    const float* on_bb  = (const float*)d_in[16];
    const float* on_m   = (const float*)d_in[17];
    const float* on_v   = (const float*)d_in[18];
    const float* ff_w   = (const float*)d_in[19];
    const float* ff_b   = (const float*)d_in[20];
    const float* ff_g   = (const float*)d_in[21];
    const float* ff_bb  = (const float*)d_in[22];
    const float* ff_m   = (const float*)d_in[23];
    const float* ff_v   = (const float*)d_in[24];
    float* out = (float*)d_out;

    float *ph, *pg, *pqk, *pwpe, *patt, *py;
    cudaGetSymbolAddress((void**)&ph,   d_h);
    cudaGetSymbolAddress((void**)&pg,   d_g);
    cudaGetSymbolAddress((void**)&pqk,  d_qk);
    cudaGetSymbolAddress((void**)&pwpe, d_wpe);
    cudaGetSymbolAddress((void**)&patt, d_att);
    cudaGetSymbolAddress((void**)&py,   d_y);

    dim3 blk(256);

    // K0: wpe[o,p] = qkv_w @ pe + qkv_b   (single "batch")
    conv1x1_kernel<MODE_BIAS><<<dim3(Pp / 64, 2, 1), blk>>>(
        pe, qkv_w, qkv_b, nullptr, nullptr, nullptr, nullptr, nullptr, nullptr,
        pwpe, Cc, OQKV);

    // K1: h = gcn conv
    conv1x1_kernel<MODE_BIAS><<<dim3(Pp / 64, 1, Nn), blk>>>(
        x, gcn_w, gcn_b, nullptr, nullptr, nullptr, nullptr, nullptr, nullptr,
        ph, Cc, Cc);

    // K2: g = relu(bn(A @ h) + x)
    adj_bn_relu_kernel<<<dim3(4, (Nn * Cc * Tt) / 64), blk>>>(
        ph, A, x, gcn_g, gcn_bb, gcn_m, gcn_v, pg);

    // K3: qk = qkv_w @ g + wpe   (pe folded into wpe)
    conv1x1_kernel<MODE_ADD2D><<<dim3(Pp / 64, 2, Nn), blk>>>(
        pg, qkv_w, nullptr, pwpe, nullptr, nullptr, nullptr, nullptr, nullptr,
        pqk, Cc, OQKV);

    // K4: attention scores
    attn_kernel<<<dim3(Hh, Nn), blk>>>(pqk, alphas, att1s, patt);

    // K5: y einsum
    y_kernel<<<dim3(4, HC, Nn), blk>>>(pg, patt, py);

    // K6: z = leaky(bn(on_w @ y + on_b) + g)   (reuse d_h as z)
    conv1x1_kernel<MODE_BN_RES_LEAKY><<<dim3(Pp / 64, 1, Nn), blk>>>(
        py, on_w, on_b, nullptr, pg, on_g, on_bb, on_m, on_v,
        ph, HC, Cc);

    // K7: out = leaky(bn(ff_w @ z + ff_b) + g)
    conv1x1_kernel<MODE_BN_RES_LEAKY><<<dim3(Pp / 64, 1, Nn), blk>>>(
        ph, ff_w, ff_b, nullptr, pg, ff_g, ff_bb, ff_m, ff_v,
        out, Cc, Cc);
}

// round 2
// speedup vs baseline: 1.5431x; 1.5431x over previous
#include <cuda_runtime.h>
#include <math.h>

// Problem constants
#define Nn   32
#define Cc   64
#define Tt   64
#define Vv   204
#define Hh   3
#define QKd  16
#define Pp   (Tt * Vv)        // 13056
#define OQKV (2 * Hh * QKd)   // 96
#define HC   (Hh * Cc)        // 192

// ---------------- scratch (device globals) ----------------
__device__ float d_h   [(size_t)Nn * Cc * Pp];     // gcn conv out; reused as z later
__device__ float d_g   [(size_t)Nn * Cc * Pp];     // relu(bn(adj)+x)
__device__ float d_qk  [(size_t)Nn * OQKV * Pp];
__device__ float d_wpe [(size_t)OQKV * Pp];        // qkv_w @ pe + qkv_b
__device__ float d_att [(size_t)Nn * Hh * Tt * Tt];
__device__ float d_attp[(size_t)2 * Nn * Hh * Tt * Tt]; // split-K partials
__device__ float d_y   [(size_t)Nn * HC * Pp];

enum { MODE_BIAS = 0, MODE_ADD2D = 1, MODE_BN_RES_LEAKY = 2 };

// ============================================================================
// conv1x1: out[n,o,p] = sum_c W[o,c] * in[n,c,p]
// P-tile 256, O-tile 64, k-chunk 16, 256 threads, 8x8 microtile.
// warp w -> o0 = w*8 (broadcast weight frag); lane px -> p frags px*4, 128+px*4
// ============================================================================
template <int MODE>
__global__ __launch_bounds__(256, 2)
void conv1x1_kernel(const float* __restrict__ in,   // [nb, Kc, P]
                    const float* __restrict__ W,    // [Oc, Kc]
                    const float* __restrict__ bias,
                    const float* __restrict__ add2d,// [Oc, P]
                    const float* __restrict__ res,  // [nb, Oc, P]
                    const float* __restrict__ bng, const float* __restrict__ bnb,
                    const float* __restrict__ bnm, const float* __restrict__ bnv,
                    float* __restrict__ out,
                    int Kc, int Oc)
{
    __shared__ float Is[16][256];
    __shared__ float Ws[16][68];

    const int n   = blockIdx.z;
    const int pt  = blockIdx.x * 256;
    const int ot  = blockIdx.y * 64;
    const int tid = threadIdx.x;
    const int px  = tid & 31;
    const int wy  = tid >> 5;
    const int o0  = wy * 8;
    const int pA  = px * 4;
    const int pB  = 128 + px * 4;

    const float* inN = in + (size_t)n * Kc * Pp + pt;
    const int wo = tid >> 2;         // 0..63
    const int wk = (tid & 3) * 4;    // 0,4,8,12

    float acc[8][8] = {};
    float4 ibuf[4];
    float4 wbuf;

    // prefetch chunk 0
    #pragma unroll
    for (int i = 0; i < 4; i++) {
        int e = tid + 256 * i;
        int k = e >> 6, f = e & 63;
        ibuf[i] = *(const float4*)(inN + (size_t)k * Pp + f * 4);
    }
    wbuf = (ot + wo < Oc) ? *(const float4*)(W + (size_t)(ot + wo) * Kc + wk)
                          : make_float4(0.f, 0.f, 0.f, 0.f);

    for (int kb = 0; kb < Kc; kb += 16) {
        #pragma unroll
        for (int i = 0; i < 4; i++) {
            int e = tid + 256 * i;
            int k = e >> 6, f = e & 63;
            *(float4*)&Is[k][f * 4] = ibuf[i];
        }
        Ws[wk + 0][wo] = wbuf.x;
        Ws[wk + 1][wo] = wbuf.y;
        Ws[wk + 2][wo] = wbuf.z;
        Ws[wk + 3][wo] = wbuf.w;
        __syncthreads();

        if (kb + 16 < Kc) {
            const float* inNext = inN + (size_t)(kb + 16) * Pp;
            #pragma unroll
            for (int i = 0; i < 4; i++) {
                int e = tid + 256 * i;
                int k = e >> 6, f = e & 63;
                ibuf[i] = *(const float4*)(inNext + (size_t)k * Pp + f * 4);
            }
            wbuf = (ot + wo < Oc) ? *(const float4*)(W + (size_t)(ot + wo) * Kc + kb + 16 + wk)
                                  : make_float4(0.f, 0.f, 0.f, 0.f);
        }

        #pragma unroll
        for (int k = 0; k < 16; k++) {
            float4 w0 = *(const float4*)&Ws[k][o0];
            float4 w1 = *(const float4*)&Ws[k][o0 + 4];
            float4 a  = *(const float4*)&Is[k][pA];
            float4 b  = *(const float4*)&Is[k][pB];
            float wv[8] = {w0.x, w0.y, w0.z, w0.w, w1.x, w1.y, w1.z, w1.w};
            float iv[8] = {a.x, a.y, a.z, a.w, b.x, b.y, b.z, b.w};
            #pragma unroll
            for (int i = 0; i < 8; i++)
                #pragma unroll
                for (int j = 0; j < 8; j++)
                    acc[i][j] = fmaf(wv[i], iv[j], acc[i][j]);
        }
        __syncthreads();
    }

    #pragma unroll
    for (int i = 0; i < 8; i++) {
        int o = ot + o0 + i;
        if (o >= Oc) continue;
        size_t obase = ((size_t)n * Oc + o) * Pp + pt;
        if (MODE == MODE_BIAS) {
            float b = bias[o];
            float4 r0 = make_float4(acc[i][0] + b, acc[i][1] + b, acc[i][2] + b, acc[i][3] + b);
            float4 r1 = make_float4(acc[i][4] + b, acc[i][5] + b, acc[i][6] + b, acc[i][7] + b);
            *(float4*)(out + obase + pA) = r0;
            *(float4*)(out + obase + pB) = r1;
        } else if (MODE == MODE_ADD2D) {
            size_t abase = (size_t)o * Pp + pt;
            float4 a0 = *(const float4*)(add2d + abase + pA);
            float4 a1 = *(const float4*)(add2d + abase + pB);
            float4 r0 = make_float4(acc[i][0] + a0.x, acc[i][1] + a0.y, acc[i][2] + a0.z, acc[i][3] + a0.w);
            float4 r1 = make_float4(acc[i][4] + a1.x, acc[i][5] + a1.y, acc[i][6] + a1.z, acc[i][7] + a1.w);
            *(float4*)(out + obase + pA) = r0;
            *(float4*)(out + obase + pB) = r1;
        } else { // MODE_BN_RES_LEAKY
            float b  = bias[o];
            float s  = bng[o] * rsqrtf(bnv[o] + 1e-5f);
            float sh = bnb[o] - bnm[o] * s + b * s;
            float4 x0 = *(const float4*)(res + obase + pA);
            float4 x1 = *(const float4*)(res + obase + pB);
            float v0[4] = {x0.x, x0.y, x0.z, x0.w};
            float v1[4] = {x1.x, x1.y, x1.z, x1.w};
            float4 r0, r1;
            float* p0 = &r0.x; float* p1 = &r1.x;
            #pragma unroll
            for (int j = 0; j < 4; j++) {
                float va = acc[i][j] * s + sh + v0[j];
                float vb = acc[i][j + 4] * s + sh + v1[j];
                p0[j] = (va > 0.f) ? va : 0.1f * va;
                p1[j] = (vb > 0.f) ? vb : 0.1f * vb;
            }
            *(float4*)(out + obase + pA) = r0;
            *(float4*)(out + obase + pB) = r1;
        }
    }
}

// ============================================================================
// adjacency: g[r,u] = relu( bn_c( sum_v h[r,v]*A[u,v] ) + x[r,u] )
// r = n*C*T + c*T + t (131072 rows). R-tile 256, U-tile 64, k-chunk 16.
// warp w -> u0 = w*8 (broadcast A frag); lane px -> r frags px*4, 128+px*4
// ============================================================================
__global__ __launch_bounds__(256, 2)
void adj_bn_relu_kernel(const float* __restrict__ h,
                        const float* __restrict__ A,   // [204,204]
                        const float* __restrict__ x,
                        const float* __restrict__ bng, const float* __restrict__ bnb,
                        const float* __restrict__ bnm, const float* __restrict__ bnv,
                        float* __restrict__ out)
{
    __shared__ float Hs[16][256];
    __shared__ float As[16][68];
    __shared__ float sS[64], shS[64];

    const int ut  = blockIdx.x * 64;
    const int rt  = blockIdx.y * 256;
    const int tid = threadIdx.x;
    const int px  = tid & 31;
    const int wy  = tid >> 5;
    const int u0  = wy * 8;
    const int pA  = px * 4;
    const int pB  = 128 + px * 4;

    if (tid < 64) {
        float s = bng[tid] * rsqrtf(bnv[tid] + 1e-5f);
        sS[tid]  = s;
        shS[tid] = bnb[tid] - bnm[tid] * s;
    }

    float acc[8][8] = {};   // [r-frag][u-frag]
    float4 hbuf[4];
    float abuf[4];

    const float* hrow = h + (size_t)(rt + tid) * Vv;

    // prefetch vb=0
    #pragma unroll
    for (int j = 0; j < 4; j++) {
        int v = j * 4;
        hbuf[j] = (v < Vv) ? *(const float4*)(hrow + v) : make_float4(0, 0, 0, 0);
    }
    #pragma unroll
    for (int i = 0; i < 4; i++) {
        int e = tid + 256 * i;
        int k = e & 15, u = e >> 4;
        abuf[i] = (ut + u < Vv && k < Vv) ? A[(size_t)(ut + u) * Vv + k] : 0.f;
    }
    __syncthreads();   // sS/shS ready

    for (int vb = 0; vb < Vv; vb += 16) {
        #pragma unroll
        for (int j = 0; j < 4; j++) {
            Hs[j * 4 + 0][tid] = hbuf[j].x;
            Hs[j * 4 + 1][tid] = hbuf[j].y;
            Hs[j * 4 + 2][tid] = hbuf[j].z;
            Hs[j * 4 + 3][tid] = hbuf[j].w;
        }
        #pragma unroll
        for (int i = 0; i < 4; i++) {
            int e = tid + 256 * i;
            int k = e & 15, u = e >> 4;
            As[k][u] = abuf[i];
        }
        __syncthreads();

        int vn = vb + 16;
        if (vn < Vv) {
            #pragma unroll
            for (int j = 0; j < 4; j++) {
                int v = vn + j * 4;
                hbuf[j] = (v < Vv) ? *(const float4*)(hrow + v) : make_float4(0, 0, 0, 0);
            }
            #pragma unroll
            for (int i = 0; i < 4; i++) {
                int e = tid + 256 * i;
                int k = e & 15, u = e >> 4;
                abuf[i] = (ut + u < Vv && vn + k < Vv) ? A[(size_t)(ut + u) * Vv + vn + k] : 0.f;
            }
        }

        #pragma unroll
        for (int k = 0; k < 16; k++) {
            float4 a0 = *(const float4*)&As[k][u0];
            float4 a1 = *(const float4*)&As[k][u0 + 4];
            float4 hA = *(const float4*)&Hs[k][pA];
            float4 hB = *(const float4*)&Hs[k][pB];
            float uv[8] = {a0.x, a0.y, a0.z, a0.w, a1.x, a1.y, a1.z, a1.w};
            float rv[8] = {hA.x, hA.y, hA.z, hA.w, hB.x, hB.y, hB.z, hB.w};
            #pragma unroll
            for (int i = 0; i < 8; i++)
                #pragma unroll
                for (int j = 0; j < 8; j++)
                    acc[i][j] = fmaf(rv[i], uv[j], acc[i][j]);
        }
        __syncthreads();
    }

    #pragma unroll
    for (int i = 0; i < 8; i++) {
        int r = rt + ((i < 4) ? (pA + i) : (pB + i - 4));
        int c = (r >> 6) & 63;
        float s  = sS[c];
        float sh = shS[c];
        size_t rbase = (size_t)r * Vv;
        #pragma unroll
        for (int jj = 0; jj < 8; jj += 4) {
            int u = ut + u0 + jj;
            if (u < Vv) {
                float4 xv = *(const float4*)(x + rbase + u);
                float xx[4] = {xv.x, xv.y, xv.z, xv.w};
                float4 rr;
                float* pr = &rr.x;
                #pragma unroll
                for (int q = 0; q < 4; q++) {
                    float val = acc[i][jj + q] * s + sh + xx[q];
                    pr[q] = fmaxf(val, 0.f);
                }
                *(float4*)(out + rbase + u) = rr;
            }
        }
    }
}

// ============================================================================
// attention partial: part[z,n,h,t,q] = sum_{c in half z, v} q[c,t,v]*k[c,q,v]
// ============================================================================
__global__ __launch_bounds__(256)
void attn_partial_kernel(const float* __restrict__ qk,
                         float* __restrict__ part)
{
    __shared__ float Qs[32][68];
    __shared__ float Ks[32][68];

    const int hh = blockIdx.x;
    const int n  = blockIdx.y;
    const int z  = blockIdx.z;
    const int c0 = z * 8;
    const int tid = threadIdx.x;
    const int t0 = (tid >> 4) * 4;
    const int q0 = (tid & 15) * 4;

    const float* qb = qk + ((size_t)n * OQKV + hh * QKd) * Pp;
    const float* kb = qk + ((size_t)n * OQKV + Hh * QKd + hh * QKd) * Pp;

    float acc[4][4] = {};

    for (int c = c0; c < c0 + 8; c++) {
        for (int vb = 0; vb < Vv; vb += 32) {
            #pragma unroll
            for (int i = 0; i < 8; i++) {
                int e  = tid + 256 * i;
                int vv = e & 31;
                int t  = e >> 5;
                int v  = vb + vv;
                bool ok = (v < Vv);
                Qs[vv][t] = ok ? qb[(size_t)c * Pp + t * Vv + v] : 0.f;
                Ks[vv][t] = ok ? kb[(size_t)c * Pp + t * Vv + v] : 0.f;
            }
            __syncthreads();
            #pragma unroll
            for (int vv = 0; vv < 32; vv++) {
                float4 qv = *(const float4*)&Qs[vv][t0];
                float4 kv = *(const float4*)&Ks[vv][q0];
                float qq[4] = {qv.x, qv.y, qv.z, qv.w};
                float kk[4] = {kv.x, kv.y, kv.z, kv.w};
                #pragma unroll
                for (int i = 0; i < 4; i++)
                    #pragma unroll
                    for (int j = 0; j < 4; j++)
                        acc[i][j] = fmaf(qq[i], kk[j], acc[i][j]);
            }
            __syncthreads();
        }
    }

    float* pb = part + (((size_t)z * Nn + n) * Hh + hh) * (Tt * Tt);
    #pragma unroll
    for (int i = 0; i < 4; i++)
        #pragma unroll
        for (int j = 0; j < 4; j++)
            pb[(size_t)(t0 + i) * Tt + q0 + j] = acc[i][j];
}

__global__ void attn_combine_kernel(const float* __restrict__ part,
                                    const float* __restrict__ alphas,
                                    const float* __restrict__ att1s,
                                    float* __restrict__ att)
{
    int idx = blockIdx.x * blockDim.x + threadIdx.x;
    const int total = Nn * Hh * Tt * Tt;
    if (idx >= total) return;
    int tq = idx & (Tt * Tt - 1);
    int h  = (idx / (Tt * Tt)) % Hh;
    float p = part[idx] + part[(size_t)total + idx];
    const float inv = 1.0f / (float)(QKd * Vv);
    att[idx] = tanhf(p * inv) * alphas[h] + att1s[(size_t)h * Tt * Tt + tq];
}

// ============================================================================
// y[n, s*C+c, q, v] = sum_t g[n,c,t,v] * att[n,s,t,q]
// per CTA: one (n, sc); output 64(q) x 204(v). k-chunk 16 over t.
// warp w -> q0 = w*8 (broadcast att frag); lane px -> v frags px*4, 128+px*4
// ============================================================================
__global__ __launch_bounds__(256, 2)
void y_kernel(const float* __restrict__ g,
              const float* __restrict__ att,
              float* __restrict__ y)
{
    __shared__ float Gs[16][256];
    __shared__ float As2[16][64];

    const int sc = blockIdx.x;    // s*64 + c
    const int n  = blockIdx.y;
    const int s  = sc >> 6;
    const int c  = sc & 63;
    const int tid = threadIdx.x;
    const int px  = tid & 31;
    const int wy  = tid >> 5;
    const int q0  = wy * 8;
    const int pA  = px * 4;
    const int pB  = 128 + px * 4;

    const float* attB = att + ((size_t)n * Hh + s) * (Tt * Tt);
    const float* gB   = g + ((size_t)n * Cc + c) * Pp;

    const int ak = tid >> 4;            // 0..15
    const int af = (tid & 15) * 4;      // 0..60

    float acc[8][8] = {};
    float4 gbuf[4];
    float4 abuf;

    // prefetch tb=0
    #pragma unroll
    for (int i = 0; i < 4; i++) {
        int e = tid + 256 * i;
        if (e < 816) {
            int k = e / 51, f = e % 51;
            gbuf[i] = *(const float4*)(gB + (size_t)k * Vv + f * 4);
        }
    }
    abuf = *(const float4*)(attB + (size_t)ak * Tt + af);

    for (int tb = 0; tb < Tt; tb += 16) {
        #pragma unroll
        for (int i = 0; i < 4; i++) {
            int e = tid + 256 * i;
            if (e < 816) {
                int k = e / 51, f = e % 51;
                *(float4*)&Gs[k][f * 4] = gbuf[i];
            }
        }
        *(float4*)&As2[ak][af] = abuf;
        __syncthreads();

        int tn = tb + 16;
        if (tn < Tt) {
            #pragma unroll
            for (int i = 0; i < 4; i++) {
                int e = tid + 256 * i;
                if (e < 816) {
                    int k = e / 51, f = e % 51;
                    gbuf[i] = *(const float4*)(gB + (size_t)(tn + k) * Vv + f * 4);
                }
            }
            abuf = *(const float4*)(attB + (size_t)(tn + ak) * Tt + af);
        }

        #pragma unroll
        for (int k = 0; k < 16; k++) {
            float4 a0 = *(const float4*)&As2[k][q0];
            float4 a1 = *(const float4*)&As2[k][q0 + 4];
            float4 gA = *(const float4*)&Gs[k][pA];
            float4 gBv = *(const float4*)&Gs[k][pB];
            float qv[8] = {a0.x, a0.y, a0.z, a0.w, a1.x, a1.y, a1.z, a1.w};
            float vv[8] = {gA.x, gA.y, gA.z, gA.w, gBv.x, gBv.y, gBv.z, gBv.w};
            #pragma unroll
            for (int i = 0; i < 8; i++)
                #pragma unroll
                for (int j = 0; j < 8; j++)
                    acc[i][j] = fmaf(qv[i], vv[j], acc[i][j]);
        }
        __syncthreads();
    }

    #pragma unroll
    for (int i = 0; i < 8; i++) {
        int q = q0 + i;
        size_t base = (((size_t)n * HC + sc) * Tt + q) * Vv;
        *(float4*)(y + base + pA) = make_float4(acc[i][0], acc[i][1], acc[i][2], acc[i][3]);
        if (pB < Vv)
            *(float4*)(y + base + pB) = make_float4(acc[i][4], acc[i][5], acc[i][6], acc[i][7]);
    }
}

// ---------------- launch ----------------
extern "C" void kernel_launch(void* const* d_in, const int* in_sizes, int n_in,
                              void* d_out, int out_size)
{
    const float* x      = (const float*)d_in[0];
    const float* A      = (const float*)d_in[1];
    const float* gcn_w  = (const float*)d_in[2];
    const float* gcn_b  = (const float*)d_in[3];
    const float* gcn_g  = (const float*)d_in[4];
    const float* gcn_bb = (const float*)d_in[5];
    const float* gcn_m  = (const float*)d_in[6];
    const float* gcn_v  = (const float*)d_in[7];
    const float* pe     = (const float*)d_in[8];
    const float* qkv_w  = (const float*)d_in[9];
    const float* qkv_b  = (const float*)d_in[10];
    const float* alphas = (const float*)d_in[11];
    const float* att1s  = (const float*)d_in[12];
    const float* on_w   = (const float*)d_in[13];
    const float* on_b   = (const float*)d_in[14];
    const float* on_g   = (const float*)d_in[15];
    const float* on_bb  = (const float*)d_in[16];
    const float* on_m   = (const float*)d_in[17];
    const float* on_v   = (const float*)d_in[18];
    const float* ff_w   = (const float*)d_in[19];
    const float* ff_b   = (const float*)d_in[20];
    const float* ff_g   = (const float*)d_in[21];
    const float* ff_bb  = (const float*)d_in[22];
    const float* ff_m   = (const float*)d_in[23];
    const float* ff_v   = (const float*)d_in[24];
    float* out = (float*)d_out;

    float *ph, *pg, *pqk, *pwpe, *patt, *pattp, *py;
    cudaGetSymbolAddress((void**)&ph,    d_h);
    cudaGetSymbolAddress((void**)&pg,    d_g);
    cudaGetSymbolAddress((void**)&pqk,   d_qk);
    cudaGetSymbolAddress((void**)&pwpe,  d_wpe);
    cudaGetSymbolAddress((void**)&patt,  d_att);
    cudaGetSymbolAddress((void**)&pattp, d_attp);
    cudaGetSymbolAddress((void**)&py,    d_y);

    dim3 blk(256);

    // K0: wpe = qkv_w @ pe + qkv_b
    conv1x1_kernel<MODE_BIAS><<<dim3(Pp / 256, 2, 1), blk>>>(
        pe, qkv_w, qkv_b, nullptr, nullptr, nullptr, nullptr, nullptr, nullptr,
        pwpe, Cc, OQKV);

    // K1: h = gcn conv
    conv1x1_kernel<MODE_BIAS><<<dim3(Pp / 256, 1, Nn), blk>>>(
        x, gcn_w, gcn_b, nullptr, nullptr, nullptr, nullptr, nullptr, nullptr,
        ph, Cc, Cc);

    // K2: g = relu(bn(A @ h) + x)
    adj_bn_relu_kernel<<<dim3(4, (Nn * Cc * Tt) / 256), blk>>>(
        ph, A, x, gcn_g, gcn_bb, gcn_m, gcn_v, pg);

    // K3: qk = qkv_w @ g + wpe
    conv1x1_kernel<MODE_ADD2D><<<dim3(Pp / 256, 2, Nn), blk>>>(
        pg, qkv_w, nullptr, pwpe, nullptr, nullptr, nullptr, nullptr, nullptr,
        pqk, Cc, OQKV);

    // K4: attention (split-K over c halves) + combine
    attn_partial_kernel<<<dim3(Hh, Nn, 2), blk>>>(pqk, pattp);
    attn_combine_kernel<<<(Nn * Hh * Tt * Tt + 255) / 256, blk>>>(pattp, alphas, att1s, patt);

    // K5: y einsum
    y_kernel<<<dim3(HC, Nn), blk>>>(pg, patt, py);

    // K6: z = leaky(bn(on_w @ y + on_b) + g)
    conv1x1_kernel<MODE_BN_RES_LEAKY><<<dim3(Pp / 256, 1, Nn), blk>>>(
        py, on_w, on_b, nullptr, pg, on_g, on_bb, on_m, on_v,
        ph, HC, Cc);

    // K7: out = leaky(bn(ff_w @ z + ff_b) + g)
    conv1x1_kernel<MODE_BN_RES_LEAKY><<<dim3(Pp / 256, 1, Nn), blk>>>(
        ph, ff_w, ff_b, nullptr, pg, ff_g, ff_bb, ff_m, ff_v,
        out, Cc, Cc);
}

// round 3
// speedup vs baseline: 2.6956x; 1.7469x over previous
#include <cuda_runtime.h>
#include <math.h>
#include <stdint.h>

// Problem constants
#define Nn   32
#define Cc   64
#define Tt   64
#define Vv   204
#define Hh   3
#define QKd  16
#define Pp   13056
#define OQKV 96
#define HC   192

// ---------------- scratch ----------------
__device__ float d_h   [(size_t)Nn * Cc * Pp];
__device__ float d_g   [(size_t)Nn * Cc * Pp];
__device__ float d_qk  [(size_t)Nn * OQKV * Pp];
__device__ float d_wpe [(size_t)OQKV * Pp];
__device__ float d_att [(size_t)Nn * Hh * Tt * Tt];
__device__ float d_attp[(size_t)2 * Nn * Hh * Tt * Tt];
__device__ float d_y   [(size_t)Nn * HC * Pp];

enum { MODE_BIAS = 0, MODE_ADD2D = 1, MODE_BN_RES_LEAKY = 2 };

// ---------------- helpers ----------------
__device__ __forceinline__ unsigned cvt_tf32(float f) {
    unsigned u;
    asm("cvt.rna.tf32.f32 %0, %1;" : "=r"(u) : "f"(f));
    return u;
}

__device__ __forceinline__ void mma8(float* d, const unsigned* a, const unsigned* b) {
    asm volatile(
        "mma.sync.aligned.m16n8k8.row.col.f32.tf32.tf32.f32 "
        "{%0,%1,%2,%3},{%4,%5,%6,%7},{%8,%9},{%0,%1,%2,%3};"
        : "+f"(d[0]), "+f"(d[1]), "+f"(d[2]), "+f"(d[3])
        : "r"(a[0]), "r"(a[1]), "r"(a[2]), "r"(a[3]), "r"(b[0]), "r"(b[1]));
}

__device__ __forceinline__ void cpa16(uint32_t dst, const void* src) {
    asm volatile("cp.async.cg.shared.global [%0],[%1],16;" :: "r"(dst), "l"(src));
}
__device__ __forceinline__ void cpa16z(uint32_t dst, const void* src, int sz) {
    asm volatile("cp.async.cg.shared.global [%0],[%1],16,%2;" :: "r"(dst), "l"(src), "r"(sz));
}
#define CP_COMMIT() asm volatile("cp.async.commit_group;")
#define CP_WAIT0()  asm volatile("cp.async.wait_group 0;")
#define CP_WAIT1()  asm volatile("cp.async.wait_group 1;")

// ============================================================================
// conv_mma: out[n,o,p] = sum_c W[o,c]*in[n,c,p]
// CTA tile: M=64 (Oc), N=256 (P), k-chunk 16, double-buffered cp.async.
// Warps 8 = 2(M,32)x4(N,64). tf32 mma m16n8k8.
// ============================================================================
template <int MODE>
__global__ __launch_bounds__(256, 2)
void conv_mma(const float* __restrict__ in, const float* __restrict__ W,
              const float* __restrict__ bias, const float* __restrict__ add2d,
              const float* __restrict__ res,
              const float* __restrict__ bng, const float* __restrict__ bnb,
              const float* __restrict__ bnm, const float* __restrict__ bnv,
              float* __restrict__ out, int Kc, int Oc)
{
    __shared__ float As[2][64][20];    // W tile [m][k], stride 20 (conflict-free)
    __shared__ float Bs[2][16][264];   // In tile [k][n], stride 264 (conflict-free)

    const int n  = blockIdx.z;
    const int pt = blockIdx.x * 256;
    const int ot = blockIdx.y * 64;
    const int tid = threadIdx.x, lane = tid & 31, warp = tid >> 5;
    const int wm = warp & 1, wn = warp >> 1;
    const int m0 = wm * 32, n0 = wn * 64;
    const int lr = lane >> 2, kc = lane & 3;

    const float* inN = in + (size_t)n * Kc * Pp + pt;
    const int wm_row = tid >> 2;      // loader: W row 0..63
    const int wgrp   = tid & 3;       // loader: k group

    float acc[2][8][4];
    #pragma unroll
    for (int f = 0; f < 2; f++)
        #pragma unroll
        for (int j = 0; j < 8; j++)
            #pragma unroll
            for (int q = 0; q < 4; q++) acc[f][j][q] = 0.f;

    const int nchunks = Kc / 16;
    uint4 wreg;

    // prologue: chunk 0
    {
        #pragma unroll
        for (int i = 0; i < 4; i++) {
            int e = tid + 256 * i;
            int k = e >> 6, grp = e & 63;
            cpa16((uint32_t)__cvta_generic_to_shared(&Bs[0][k][grp * 4]),
                  inN + (size_t)k * Pp + grp * 4);
        }
        CP_COMMIT();
        int o = ot + wm_row;
        float4 w = (o < Oc) ? *(const float4*)(W + (size_t)o * Kc + wgrp * 4)
                            : make_float4(0.f, 0.f, 0.f, 0.f);
        wreg = make_uint4(cvt_tf32(w.x), cvt_tf32(w.y), cvt_tf32(w.z), cvt_tf32(w.w));
        *(uint4*)&As[0][wm_row][wgrp * 4] = wreg;
    }

    for (int c = 0; c < nchunks; c++) {
        const int buf = c & 1;
        if (c + 1 < nchunks) {
            const float* base = inN + (size_t)(c + 1) * 16 * Pp;
            #pragma unroll
            for (int i = 0; i < 4; i++) {
                int e = tid + 256 * i;
                int k = e >> 6, grp = e & 63;
                cpa16((uint32_t)__cvta_generic_to_shared(&Bs[buf ^ 1][k][grp * 4]),
                      base + (size_t)k * Pp + grp * 4);
            }
            CP_COMMIT();
            int o = ot + wm_row;
            float4 w = (o < Oc) ? *(const float4*)(W + (size_t)o * Kc + (c + 1) * 16 + wgrp * 4)
                                : make_float4(0.f, 0.f, 0.f, 0.f);
            wreg = make_uint4(cvt_tf32(w.x), cvt_tf32(w.y), cvt_tf32(w.z), cvt_tf32(w.w));
            CP_WAIT1();
        } else {
            CP_WAIT0();
        }
        __syncthreads();

        #pragma unroll
        for (int g = 0; g < 2; g++) {
            unsigned a[2][4];
            #pragma unroll
            for (int f = 0; f < 2; f++) {
                a[f][0] = __float_as_uint(As[buf][m0 + f * 16 + lr    ][g * 8 + kc    ]);
                a[f][1] = __float_as_uint(As[buf][m0 + f * 16 + lr + 8][g * 8 + kc    ]);
                a[f][2] = __float_as_uint(As[buf][m0 + f * 16 + lr    ][g * 8 + kc + 4]);
                a[f][3] = __float_as_uint(As[buf][m0 + f * 16 + lr + 8][g * 8 + kc + 4]);
            }
            #pragma unroll
            for (int j = 0; j < 8; j++) {
                unsigned b[2];
                b[0] = __float_as_uint(Bs[buf][g * 8 + kc    ][n0 + 8 * j + lr]);
                b[1] = __float_as_uint(Bs[buf][g * 8 + kc + 4][n0 + 8 * j + lr]);
                mma8(acc[0][j], a[0], b);
                mma8(acc[1][j], a[1], b);
            }
        }
        __syncthreads();
        if (c + 1 < nchunks)
            *(uint4*)&As[buf ^ 1][wm_row][wgrp * 4] = wreg;
    }

    // epilogue: each thread owns, for frag (f,j): rows m and m+8, cols 2kc, 2kc+1
    #pragma unroll
    for (int f = 0; f < 2; f++) {
        #pragma unroll
        for (int half = 0; half < 2; half++) {
            int o = ot + m0 + f * 16 + lr + half * 8;
            if (o >= Oc) continue;
            size_t obase = ((size_t)n * Oc + o) * Pp;
            if (MODE == MODE_BIAS) {
                float b = bias[o];
                #pragma unroll
                for (int j = 0; j < 8; j++) {
                    int p = pt + n0 + 8 * j + 2 * kc;
                    *(float2*)(out + obase + p) =
                        make_float2(acc[f][j][half * 2] + b, acc[f][j][half * 2 + 1] + b);
                }
            } else if (MODE == MODE_ADD2D) {
                size_t abase = (size_t)o * Pp;
                #pragma unroll
                for (int j = 0; j < 8; j++) {
                    int p = pt + n0 + 8 * j + 2 * kc;
                    float2 av = *(const float2*)(add2d + abase + p);
                    *(float2*)(out + obase + p) =
                        make_float2(acc[f][j][half * 2] + av.x, acc[f][j][half * 2 + 1] + av.y);
                }
            } else {
                float s  = bng[o] * rsqrtf(bnv[o] + 1e-5f);
                float sh = bnb[o] - bnm[o] * s + bias[o] * s;
                #pragma unroll
                for (int j = 0; j < 8; j++) {
                    int p = pt + n0 + 8 * j + 2 * kc;
                    float2 rv = *(const float2*)(res + obase + p);
                    float va = acc[f][j][half * 2]     * s + sh + rv.x;
                    float vb = acc[f][j][half * 2 + 1] * s + sh + rv.y;
                    *(float2*)(out + obase + p) =
                        make_float2(va > 0.f ? va : 0.1f * va, vb > 0.f ? vb : 0.1f * vb);
                }
            }
        }
    }
}

// ============================================================================
// adj_mma: g[r,u] = relu(bn_c(sum_v h[r,v]*A[u,v]) + x[r,u]),  r-tile 64, u full 208
// Warps 8 = 4(M,16)x2(N,104=13 frags). K=204, k-chunk 16 (13 chunks).
// ============================================================================
__global__ __launch_bounds__(256, 2)
void adj_mma(const float* __restrict__ h, const float* __restrict__ Am,
             const float* __restrict__ x,
             const float* __restrict__ bng, const float* __restrict__ bnb,
             const float* __restrict__ bnm, const float* __restrict__ bnv,
             float* __restrict__ out)
{
    __shared__ float As[2][64][20];    // h tile [m(r)][k(v)]
    __shared__ float Bs[2][208][20];   // A tile [n(u)][k(v)]

    const int rt = blockIdx.x * 64;
    const int tid = threadIdx.x, lane = tid & 31, warp = tid >> 5;
    const int wm = warp & 3, wn = warp >> 2;
    const int m0 = wm * 16, nb0 = wn * 104;
    const int lr = lane >> 2, kc = lane & 3;

    const int ch  = (rt >> 6) & 63;    // bn channel (constant per CTA)
    const float s  = bng[ch] * rsqrtf(bnv[ch] + 1e-5f);
    const float sh = bnb[ch] - bnm[ch] * s;

    float acc[13][4];
    #pragma unroll
    for (int j = 0; j < 13; j++)
        #pragma unroll
        for (int q = 0; q < 4; q++) acc[j][q] = 0.f;

    const int am = tid >> 2;           // A-loader row 0..63
    const int aks = (tid & 3) * 4;     // A-loader k group

    const int NCH = 13;                // ceil(204/16)
    uint4 areg;

    // prologue
    {
        #pragma unroll
        for (int i = 0; i < 4; i++) {
            int e = tid + 256 * i;
            if (e < 832) {
                int u = e >> 2, grp = e & 3;
                int v0 = grp * 4;
                int ok = (u < 204 && v0 < 204);
                cpa16z((uint32_t)__cvta_generic_to_shared(&Bs[0][u][grp * 4]),
                       ok ? (Am + (size_t)u * 204 + v0) : Am, ok ? 16 : 0);
            }
        }
        CP_COMMIT();
        float v4[4];
        #pragma unroll
        for (int i = 0; i < 4; i++) {
            int v = aks + i;
            v4[i] = (v < 204) ? h[(size_t)(rt + am) * 204 + v] : 0.f;
        }
        areg = make_uint4(cvt_tf32(v4[0]), cvt_tf32(v4[1]), cvt_tf32(v4[2]), cvt_tf32(v4[3]));
        *(uint4*)&As[0][am][aks] = areg;
    }

    for (int c = 0; c < NCH; c++) {
        const int buf = c & 1;
        if (c + 1 < NCH) {
            int vb = (c + 1) * 16;
            #pragma unroll
            for (int i = 0; i < 4; i++) {
                int e = tid + 256 * i;
                if (e < 832) {
                    int u = e >> 2, grp = e & 3;
                    int v0 = vb + grp * 4;
                    int ok = (u < 204 && v0 < 204);
                    cpa16z((uint32_t)__cvta_generic_to_shared(&Bs[buf ^ 1][u][grp * 4]),
                           ok ? (Am + (size_t)u * 204 + v0) : Am, ok ? 16 : 0);
                }
            }
            CP_COMMIT();
            float v4[4];
            #pragma unroll
            for (int i = 0; i < 4; i++) {
                int v = vb + aks + i;
                v4[i] = (v < 204) ? h[(size_t)(rt + am) * 204 + v] : 0.f;
            }
            areg = make_uint4(cvt_tf32(v4[0]), cvt_tf32(v4[1]), cvt_tf32(v4[2]), cvt_tf32(v4[3]));
            CP_WAIT1();
        } else {
            CP_WAIT0();
        }
        __syncthreads();

        #pragma unroll
        for (int g = 0; g < 2; g++) {
            unsigned a[4];
            a[0] = __float_as_uint(As[buf][m0 + lr    ][g * 8 + kc    ]);
            a[1] = __float_as_uint(As[buf][m0 + lr + 8][g * 8 + kc    ]);
            a[2] = __float_as_uint(As[buf][m0 + lr    ][g * 8 + kc + 4]);
            a[3] = __float_as_uint(As[buf][m0 + lr + 8][g * 8 + kc + 4]);
            #pragma unroll
            for (int j = 0; j < 13; j++) {
                unsigned b[2];
                b[0] = __float_as_uint(Bs[buf][nb0 + 8 * j + lr][g * 8 + kc    ]);
                b[1] = __float_as_uint(Bs[buf][nb0 + 8 * j + lr][g * 8 + kc + 4]);
                mma8(acc[j], a, b);
            }
        }
        __syncthreads();
        if (c + 1 < NCH)
            *(uint4*)&As[buf ^ 1][am][aks] = areg;
    }

    #pragma unroll
    for (int half = 0; half < 2; half++) {
        int r = rt + m0 + lr + half * 8;
        size_t rbase = (size_t)r * 204;
        #pragma unroll
        for (int j = 0; j < 13; j++) {
            int u = nb0 + 8 * j + 2 * kc;
            if (u < 204) {
                float2 xv = *(const float2*)(x + rbase + u);
                float va = acc[j][half * 2]     * s + sh + xv.x;
                float vb = acc[j][half * 2 + 1] * s + sh + xv.y;
                *(float2*)(out + rbase + u) = make_float2(fmaxf(va, 0.f), fmaxf(vb, 0.f));
            }
        }
    }
}

// ============================================================================
// y_mma: y[n, s*64+c, q, v] = sum_t g[n,c,t,v] * att[n,s,t,q]
// One CTA per (c, s, n). M=64(q), N=208(v), K=64(t). Warps 4(M,16)x2(N,104).
// ============================================================================
__global__ __launch_bounds__(256, 2)
void y_mma(const float* __restrict__ g, const float* __restrict__ att,
           float* __restrict__ y)
{
    extern __shared__ float sm[];
    float (*As)[72]  = (float(*)[72])sm;                 // att tile [k(t)][m(q)]
    float (*Bs)[232] = (float(*)[232])(sm + 64 * 72);    // g tile   [k(t)][n(v)]

    const int cch = blockIdx.x, s = blockIdx.y, n = blockIdx.z;
    const int tid = threadIdx.x, lane = tid & 31, warp = tid >> 5;
    const int wm = warp & 3, wn = warp >> 2;
    const int m0 = wm * 16, nb0 = wn * 104;
    const int lr = lane >> 2, kc = lane & 3;

    const float* gB   = g + ((size_t)n * Cc + cch) * Pp;
    const float* attB = att + (size_t)(n * Hh + s) * 4096;

    // load g tile: 64 rows x 52 groups (last group zero-fill, v 204..207)
    #pragma unroll
    for (int i = 0; i < 13; i++) {
        int e = tid + 256 * i;
        if (e < 3328) {
            int t = e / 52, grp = e % 52;
            int ok = (grp < 51);
            cpa16z((uint32_t)__cvta_generic_to_shared(&Bs[t][grp * 4]),
                   ok ? (gB + (size_t)t * 204 + grp * 4) : gB, ok ? 16 : 0);
        }
    }
    CP_COMMIT();
    // load att tile (rna-converted)
    #pragma unroll
    for (int i = 0; i < 4; i++) {
        int e = tid + 256 * i;
        int t = e >> 4, grp = e & 15;
        float4 a = *(const float4*)(attB + (size_t)t * 64 + grp * 4);
        *(uint4*)&As[t][grp * 4] =
            make_uint4(cvt_tf32(a.x), cvt_tf32(a.y), cvt_tf32(a.z), cvt_tf32(a.w));
    }
    CP_WAIT0();
    __syncthreads();

    float acc[13][4];
    #pragma unroll
    for (int j = 0; j < 13; j++)
        #pragma unroll
        for (int q = 0; q < 4; q++) acc[j][q] = 0.f;

    #pragma unroll
    for (int g8 = 0; g8 < 8; g8++) {
        unsigned a[4];
        a[0] = __float_as_uint(As[g8 * 8 + kc    ][m0 + lr    ]);
        a[1] = __float_as_uint(As[g8 * 8 + kc    ][m0 + lr + 8]);
        a[2] = __float_as_uint(As[g8 * 8 + kc + 4][m0 + lr    ]);
        a[3] = __float_as_uint(As[g8 * 8 + kc + 4][m0 + lr + 8]);
        #pragma unroll
        for (int j = 0; j < 13; j++) {
            unsigned b[2];
            b[0] = __float_as_uint(Bs[g8 * 8 + kc    ][nb0 + 8 * j + lr]);
            b[1] = __float_as_uint(Bs[g8 * 8 + kc + 4][nb0 + 8 * j + lr]);
            mma8(acc[j], a, b);
        }
    }

    size_t ybase = ((size_t)n * HC + s * 64 + cch) * Pp;
    #pragma unroll
    for (int half = 0; half < 2; half++) {
        int q = m0 + lr + half * 8;
        #pragma unroll
        for (int j = 0; j < 13; j++) {
            int v = nb0 + 8 * j + 2 * kc;
            if (v < 204)
                *(float2*)(y + ybase + (size_t)q * 204 + v) =
                    make_float2(acc[j][half * 2], acc[j][half * 2 + 1]);
        }
    }
}

// ============================================================================
// attention (fp32, unchanged from round 2): split-K partials + combine
// ============================================================================
__global__ __launch_bounds__(256)
void attn_partial_kernel(const float* __restrict__ qk, float* __restrict__ part)
{
    __shared__ float Qs[32][68];
    __shared__ float Ks[32][68];

    const int hh = blockIdx.x;
    const int n  = blockIdx.y;
    const int z  = blockIdx.z;
    const int c0 = z * 8;
    const int tid = threadIdx.x;
    const int t0 = (tid >> 4) * 4;
    const int q0 = (tid & 15) * 4;

    const float* qb = qk + ((size_t)n * OQKV + hh * QKd) * Pp;
    const float* kb = qk + ((size_t)n * OQKV + Hh * QKd + hh * QKd) * Pp;

    float acc[4][4] = {};

    for (int c = c0; c < c0 + 8; c++) {
        for (int vb = 0; vb < Vv; vb += 32) {
            #pragma unroll
            for (int i = 0; i < 8; i++) {
                int e  = tid + 256 * i;
                int vv = e & 31;
                int t  = e >> 5;
                int v  = vb + vv;
                bool ok = (v < Vv);
                Qs[vv][t] = ok ? qb[(size_t)c * Pp + t * Vv + v] : 0.f;
                Ks[vv][t] = ok ? kb[(size_t)c * Pp + t * Vv + v] : 0.f;
            }
            __syncthreads();
            #pragma unroll
            for (int vv = 0; vv < 32; vv++) {
                float4 qv = *(const float4*)&Qs[vv][t0];
                float4 kv = *(const float4*)&Ks[vv][q0];
                float qq[4] = {qv.x, qv.y, qv.z, qv.w};
                float kk[4] = {kv.x, kv.y, kv.z, kv.w};
                #pragma unroll
                for (int i = 0; i < 4; i++)
                    #pragma unroll
                    for (int j = 0; j < 4; j++)
                        acc[i][j] = fmaf(qq[i], kk[j], acc[i][j]);
            }
            __syncthreads();
        }
    }

    float* pb = part + (((size_t)z * Nn + n) * Hh + hh) * (Tt * Tt);
    #pragma unroll
    for (int i = 0; i < 4; i++)
        #pragma unroll
        for (int j = 0; j < 4; j++)
            pb[(size_t)(t0 + i) * Tt + q0 + j] = acc[i][j];
}

__global__ void attn_combine_kernel(const float* __restrict__ part,
                                    const float* __restrict__ alphas,
                                    const float* __restrict__ att1s,
                                    float* __restrict__ att)
{
    int idx = blockIdx.x * blockDim.x + threadIdx.x;
    const int total = Nn * Hh * Tt * Tt;
    if (idx >= total) return;
    int tq = idx & (Tt * Tt - 1);
    int h  = (idx / (Tt * Tt)) % Hh;
    float p = part[idx] + part[(size_t)total + idx];
    const float inv = 1.0f / (float)(QKd * Vv);
    att[idx] = tanhf(p * inv) * alphas[h] + att1s[(size_t)h * Tt * Tt + tq];
}

// ---------------- launch ----------------
extern "C" void kernel_launch(void* const* d_in, const int* in_sizes, int n_in,
                              void* d_out, int out_size)
{
    const float* x      = (const float*)d_in[0];
    const float* A      = (const float*)d_in[1];
    const float* gcn_w  = (const float*)d_in[2];
    const float* gcn_b  = (const float*)d_in[3];
    const float* gcn_g  = (const float*)d_in[4];
    const float* gcn_bb = (const float*)d_in[5];
    const float* gcn_m  = (const float*)d_in[6];
    const float* gcn_v  = (const float*)d_in[7];
    const float* pe     = (const float*)d_in[8];
    const float* qkv_w  = (const float*)d_in[9];
    const float* qkv_b  = (const float*)d_in[10];
    const float* alphas = (const float*)d_in[11];
    const float* att1s  = (const float*)d_in[12];
    const float* on_w   = (const float*)d_in[13];
    const float* on_b   = (const float*)d_in[14];
    const float* on_g   = (const float*)d_in[15];
    const float* on_bb  = (const float*)d_in[16];
    const float* on_m   = (const float*)d_in[17];
    const float* on_v   = (const float*)d_in[18];
    const float* ff_w   = (const float*)d_in[19];
    const float* ff_b   = (const float*)d_in[20];
    const float* ff_g   = (const float*)d_in[21];
    const float* ff_bb  = (const float*)d_in[22];
    const float* ff_m   = (const float*)d_in[23];
    const float* ff_v   = (const float*)d_in[24];
    float* out = (float*)d_out;

    float *ph, *pg, *pqk, *pwpe, *patt, *pattp, *py;
    cudaGetSymbolAddress((void**)&ph,    d_h);
    cudaGetSymbolAddress((void**)&pg,    d_g);
    cudaGetSymbolAddress((void**)&pqk,   d_qk);
    cudaGetSymbolAddress((void**)&pwpe,  d_wpe);
    cudaGetSymbolAddress((void**)&patt,  d_att);
    cudaGetSymbolAddress((void**)&pattp, d_attp);
    cudaGetSymbolAddress((void**)&py,    d_y);

    static int smem_set = 0;
    if (!smem_set) {
        cudaFuncSetAttribute(y_mma, cudaFuncAttributeMaxDynamicSharedMemorySize,
                             (64 * 72 + 64 * 232) * 4);
        smem_set = 1;
    }
    const int ysmem = (64 * 72 + 64 * 232) * 4;

    dim3 blk(256);

    // K0: wpe = qkv_w @ pe + qkv_b
    conv_mma<MODE_BIAS><<<dim3(Pp / 256, 2, 1), blk>>>(
        pe, qkv_w, qkv_b, nullptr, nullptr, nullptr, nullptr, nullptr, nullptr,
        pwpe, Cc, OQKV);

    // K1: h = gcn conv
    conv_mma<MODE_BIAS><<<dim3(Pp / 256, 1, Nn), blk>>>(
        x, gcn_w, gcn_b, nullptr, nullptr, nullptr, nullptr, nullptr, nullptr,
        ph, Cc, Cc);

    // K2: g = relu(bn(A @ h) + x)
    adj_mma<<<dim3((Nn * Cc * Tt) / 64, 1, 1), blk>>>(
        ph, A, x, gcn_g, gcn_bb, gcn_m, gcn_v, pg);

    // K3: qk = qkv_w @ g + wpe
    conv_mma<MODE_ADD2D><<<dim3(Pp / 256, 2, Nn), blk>>>(
        pg, qkv_w, nullptr, pwpe, nullptr, nullptr, nullptr, nullptr, nullptr,
        pqk, Cc, OQKV);

    // K4: attention scores (fp32 split-K) + combine
    attn_partial_kernel<<<dim3(Hh, Nn, 2), blk>>>(pqk, pattp);
    attn_combine_kernel<<<(Nn * Hh * Tt * Tt + 255) / 256, blk>>>(pattp, alphas, att1s, patt);

    // K5: y einsum
    y_mma<<<dim3(Cc, Hh, Nn), blk, ysmem>>>(pg, patt, py);

    // K6: z = leaky(bn(on_w @ y + on_b) + g)
    conv_mma<MODE_BN_RES_LEAKY><<<dim3(Pp / 256, 1, Nn), blk>>>(
        py, on_w, on_b, nullptr, pg, on_g, on_bb, on_m, on_v,
        ph, HC, Cc);

    // K7: out = leaky(bn(ff_w @ z + ff_b) + g)
    conv_mma<MODE_BN_RES_LEAKY><<<dim3(Pp / 256, 1, Nn), blk>>>(
        ph, ff_w, ff_b, nullptr, pg, ff_g, ff_bb, ff_m, ff_v,
        out, Cc, Cc);
}